// round 8
// baseline (speedup 1.0000x reference)
#include <cuda_runtime.h>
#include <cstdint>

#define BATCH    1024
#define VOCAB    100000
#define ROWBYTES (VOCAB * 4)          // 400000, multiple of 16
#define DIM      128
#define NSEG     3
#define NBINS    2048
#define HOTCAP   3072
#define NTHREADS 512
#define CUT0 100
#define CUT1 500
#define CUT2 1000
#define TGUESS 2.0f                   // rank-1000 of 100k N(0,1) ~ 2.33
#define TILE_BYTES 16384
#define TILE_F4    (TILE_BYTES / 16)  // 1024
#define NTILES     ((ROWBYTES + TILE_BYTES - 1) / TILE_BYTES)   // 25 (last=6784B)
#define PDEPTH 4                      // pipeline depth (power of 2)

__device__ float g_rh[NSEG * BATCH * DIM];

// ---------------------------------------------------------------------------
// Kernel 1: rerank_hidden = hidden @ W[seg]^T + b[seg], tiled smem GEMM.
// ---------------------------------------------------------------------------
#define RTILE 32
#define KC 64
__global__ void __launch_bounds__(256)
rh_kernel(const float* __restrict__ hidden,
          const float* __restrict__ W,
          const float* __restrict__ bias)
{
    __shared__ float Wt[DIM][KC + 1];
    __shared__ float hs[RTILE][KC];
    const int seg = blockIdx.y;
    const int r0  = blockIdx.x * RTILE;
    const int t   = threadIdx.x;
    const int d   = t & 127;
    const int rhh = t >> 7;

    float acc[16];
#pragma unroll
    for (int i = 0; i < 16; i++) acc[i] = 0.f;
    const float* Wseg = W + (size_t)seg * DIM * DIM;

    for (int kc = 0; kc < DIM; kc += KC) {
        __syncthreads();
#pragma unroll
        for (int j = 0; j < 32; j++) {
            int e = t + j * 256;
            Wt[e >> 6][e & 63] = Wseg[(e >> 6) * DIM + kc + (e & 63)];
        }
#pragma unroll
        for (int j = 0; j < 8; j++) {
            int e = t + j * 256;
            hs[e >> 6][e & 63] = hidden[(size_t)(r0 + (e >> 6)) * DIM + kc + (e & 63)];
        }
        __syncthreads();
#pragma unroll 8
        for (int k = 0; k < KC; k++) {
            float wv = Wt[d][k];
#pragma unroll
            for (int r = 0; r < 16; r++)
                acc[r] += hs[rhh * 16 + r][k] * wv;
        }
    }
    float bv = bias[seg * DIM + d];
#pragma unroll
    for (int r = 0; r < 16; r++) {
        int row = r0 + rhh * 16 + r;
        g_rh[(size_t)seg * BATCH * DIM + (size_t)row * DIM + d] = acc[r] + bv;
    }
}

__device__ __forceinline__ unsigned mono(float f) {
    unsigned u = __float_as_uint(f);
    return (u & 0x80000000u) ? ~u : (u | 0x80000000u);
}

__device__ __forceinline__ unsigned smem_u32(const void* p) {
    return (unsigned)__cvta_generic_to_shared(p);
}

__device__ __forceinline__ void mbar_wait(unsigned mbar, int phase) {
    asm volatile(
        "{\n\t.reg .pred P;\n\t"
        "W_%=:\n\t"
        "mbarrier.try_wait.parity.acquire.cta.shared::cta.b64 P, [%0], %1, 0x989680;\n\t"
        "@P bra D_%=;\n\t"
        "bra W_%=;\n\t"
        "D_%=:\n\t}"
        :: "r"(mbar), "r"(phase) : "memory");
}

// Issue a TMA bulk load of tile t into sbuf[buf] (single thread).
__device__ __forceinline__ void tma_load_tile(const char* gsrc, void* sdst,
                                              unsigned mbar, int t)
{
    int nbytes = (t == NTILES - 1) ? (ROWBYTES - t * TILE_BYTES) : TILE_BYTES;
    asm volatile("mbarrier.arrive.expect_tx.shared.b64 _, [%0], %1;"
                 :: "r"(mbar), "r"(nbytes) : "memory");
    asm volatile(
        "cp.async.bulk.shared::cluster.global.mbarrier::complete_tx::bytes "
        "[%0], [%1], %2, [%3];"
        :: "r"(smem_u32(sdst)), "l"(gsrc + (size_t)t * TILE_BYTES),
           "r"(nbytes), "r"(mbar) : "memory");
}

// ---------------------------------------------------------------------------
// Scan NBINS-bin histogram descending with shfl; 4 bins per thread.
// ---------------------------------------------------------------------------
__device__ void scan_find(unsigned* hist, unsigned* warpsum, int tid,
                          int* s_bin, int* s_rank)
{
    const int lane = tid & 31, w = tid >> 5;
    unsigned c[4];
    unsigned chunk = 0;
#pragma unroll
    for (int j = 0; j < 4; j++) {
        c[j] = hist[NBINS - 1 - 4 * tid - j];
        chunk += c[j];
    }
    unsigned pfx = chunk;
#pragma unroll
    for (int off = 1; off < 32; off <<= 1) {
        unsigned n = __shfl_up_sync(0xFFFFFFFFu, pfx, off);
        if (lane >= off) pfx += n;
    }
    if (lane == 31) warpsum[w] = pfx;
    __syncthreads();
    if (w == 0) {
        unsigned s = (lane < 16) ? warpsum[lane] : 0u;
#pragma unroll
        for (int off = 1; off < 16; off <<= 1) {
            unsigned n = __shfl_up_sync(0xFFFFFFFFu, s, off);
            if (lane >= off) s += n;
        }
        if (lane < 16) warpsum[lane] = s;
    }
    __syncthreads();
    unsigned wbase = (w > 0) ? warpsum[w - 1] : 0u;
    unsigned incl = wbase + pfx;
    unsigned excl = incl - chunk;
    const unsigned Ks[3] = {CUT0, CUT1, CUT2};
#pragma unroll
    for (int kk = 0; kk < 3; kk++) {
        unsigned K = Ks[kk];
        if (excl < K && K <= incl) {
            unsigned cc = excl;
#pragma unroll
            for (int j = 0; j < 4; j++) {
                unsigned h = c[j];
                if (cc < K && K <= cc + h) {
                    s_bin[kk]  = NBINS - 1 - 4 * tid - j;
                    s_rank[kk] = (int)(K - cc);
                    break;
                }
                cc += h;
            }
        }
    }
    __syncthreads();
}

__device__ __forceinline__ void push_cand(float v, int gi,
                                          unsigned long long* hot, unsigned* hist,
                                          int& slot)
{
    unsigned m = mono(v);
    if (slot < HOTCAP) {
        hot[slot] = ((unsigned long long)m << 32) | (unsigned)(~gi);
        unsigned fb = (m - 0xC0000000u) >> 13;
        if (fb > (NBINS - 1u)) fb = NBINS - 1u;
        atomicAdd(&hist[fb], 1u);
    }
    slot++;
}

// ---------------------------------------------------------------------------
// Kernel 2: one CTA per row. Depth-4 TMA pipeline: bulk in, bulk out, SMEM scan.
// ---------------------------------------------------------------------------
__global__ void __launch_bounds__(NTHREADS, 2)
rerank_tma_kernel(const float* __restrict__ logits,
                  const float* __restrict__ emb,
                  float* __restrict__ out)
{
    __shared__ __align__(128) float4 sbuf[PDEPTH][TILE_F4];   // 4 x 16 KB
    __shared__ unsigned long long hot[HOTCAP];                // 24 KB
    __shared__ unsigned hist[NBINS];                          // 8 KB (reused as res)
    __shared__ float rh[NSEG * DIM];
    __shared__ unsigned warpsum[16];
    __shared__ unsigned long long Tkey[3];
    __shared__ __align__(8) unsigned long long mbar[PDEPTH];
    __shared__ int s_bin[3];
    __shared__ int s_rank[3];
    __shared__ int s_nhot;
    __shared__ int s_dcnt;

    const int row = blockIdx.x;
    const int tid = threadIdx.x;
    const int lane = tid & 31;
    const unsigned BASE = 0xC0000000u;                        // mono(2.0f)

    for (int i = tid; i < NBINS; i += NTHREADS) hist[i] = 0u;
    if (tid < NSEG * DIM) {
        int seg = tid >> 7, d = tid & 127;
        rh[tid] = g_rh[(size_t)seg * BATCH * DIM + (size_t)row * DIM + d];
    }
    if (tid == 0) {
        s_nhot = 0; s_dcnt = 0;
#pragma unroll
        for (int b = 0; b < PDEPTH; b++)
            asm volatile("mbarrier.init.shared.b64 [%0], 1;"
                         :: "r"(smem_u32(&mbar[b])) : "memory");
    }
    __syncthreads();

    const char* gsrc = (const char*)(logits) + (size_t)row * ROWBYTES;
    char*       gdst = (char*)(out)          + (size_t)row * ROWBYTES;
    float*      outrow = out + (size_t)row * VOCAB;

    // ---- Prologue: fill the pipeline with PDEPTH loads ----
    if (tid == 0) {
#pragma unroll
        for (int t = 0; t < PDEPTH; t++)
            tma_load_tile(gsrc, &sbuf[t][0], smem_u32(&mbar[t]), t);
    }

    // ---- Steady state ----
    for (int t = 0; t < NTILES; t++) {
        const int buf = t & (PDEPTH - 1);
        const int phase = (t >> 2) & 1;             // PDEPTH = 4
        const int nbytes = (t == NTILES - 1) ? (ROWBYTES - t * TILE_BYTES) : TILE_BYTES;

        mbar_wait(smem_u32(&mbar[buf]), phase);     // tile t arrived

        if (tid == 0) {                             // bulk store (reads SMEM, like scan)
            asm volatile(
                "cp.async.bulk.global.shared::cta.bulk_group [%0], [%1], %2;"
                :: "l"(gdst + (size_t)t * TILE_BYTES), "r"(smem_u32(&sbuf[buf][0])),
                   "r"(nbytes) : "memory");
            asm volatile("cp.async.bulk.commit_group;" ::: "memory");
        }

        // ---- scan tile from SMEM ----
        const int nf4 = nbytes >> 4;
        const int gbase = t * TILE_F4;
        for (int k0 = 0; k0 < nf4; k0 += NTHREADS) {
            int k = k0 + tid;
            bool in = k < nf4;
            float4 v = in ? sbuf[buf][k] : make_float4(0.f, 0.f, 0.f, 0.f);
            float M = fmaxf(fmaxf(v.x, v.y), fmaxf(v.z, v.w));
            unsigned m4 = 0;
            int cnt = 0;
            if (M > TGUESS) {
                m4 = (v.x > TGUESS) | ((v.y > TGUESS) << 1)
                   | ((v.z > TGUESS) << 2) | ((v.w > TGUESS) << 3);
                cnt = __popc(m4);
            }
            if (__ballot_sync(0xFFFFFFFFu, cnt > 0)) {
                int pfx = cnt;
#pragma unroll
                for (int off = 1; off < 32; off <<= 1) {
                    int n = __shfl_up_sync(0xFFFFFFFFu, pfx, off);
                    if (lane >= off) pfx += n;
                }
                int total = __shfl_sync(0xFFFFFFFFu, pfx, 31);
                int wbase = 0;
                if (lane == 31) wbase = atomicAdd(&s_nhot, total);
                wbase = __shfl_sync(0xFFFFFFFFu, wbase, 31);
                int slot = wbase + pfx - cnt;
                if (cnt) {
                    int gi = 4 * (gbase + k);
                    if (m4 & 1) push_cand(v.x, gi + 0, hot, hist, slot);
                    if (m4 & 2) push_cand(v.y, gi + 1, hot, hist, slot);
                    if (m4 & 4) push_cand(v.z, gi + 2, hot, hist, slot);
                    if (m4 & 8) push_cand(v.w, gi + 3, hot, hist, slot);
                }
            }
        }
        __syncthreads();                             // scan of buf done (all threads)

        // ---- refill: load tile t+PDEPTH into this buffer ----
        if (tid == 0 && t + PDEPTH < NTILES) {
            // ensure the bulk store from this buffer finished READING smem
            asm volatile("cp.async.bulk.wait_group.read 0;" ::: "memory");
            tma_load_tile(gsrc, &sbuf[buf][0], smem_u32(&mbar[buf]), t + PDEPTH);
        }
    }
    __syncthreads();

    int nhot = s_nhot;
    bool fast = (nhot >= CUT2) && (nhot <= HOTCAP);

    if (fast) {
        scan_find(hist, warpsum, tid, s_bin, s_rank);
        const int b0 = s_bin[0], b1 = s_bin[1], b2 = s_bin[2];
        for (int i = tid; i < nhot; i += NTHREADS) {
            unsigned long long k = hot[i];
            unsigned fb = ((unsigned)(k >> 32) - BASE) >> 13;
            if (fb > (NBINS - 1u)) fb = NBINS - 1u;
            int bin = (int)fb;
            bool m0 = (bin == b0), m1 = (bin == b1), m2 = (bin == b2);
            if (m0 | m1 | m2) {
                int cnt = 0;
                for (int j = 0; j < nhot; j++) {
                    unsigned long long kj = hot[j];
                    unsigned fbj = ((unsigned)(kj >> 32) - BASE) >> 13;
                    if (fbj > (NBINS - 1u)) fbj = NBINS - 1u;
                    if ((int)fbj == bin && kj > k) cnt++;
                }
                int r = cnt + 1;
                if (m0 && r == s_rank[0]) Tkey[0] = k;
                if (m1 && r == s_rank[1]) Tkey[1] = k;
                if (m2 && r == s_rank[2]) Tkey[2] = k;
            }
        }
        __syncthreads();
    } else {
        // ---- Fallback: coarse histogram over the whole row (global re-read) ----
        for (int i = tid; i < NBINS; i += NTHREADS) hist[i] = 0u;
        if (tid == 0) s_nhot = 0;
        __syncthreads();
        const float4* row4 = (const float4*)(logits + (size_t)row * VOCAB);
        const int NV4 = VOCAB / 4;
        for (int i = tid; i < NV4; i += NTHREADS) {
            float4 v = row4[i];
            atomicAdd(&hist[mono(v.x) >> 21], 1u);
            atomicAdd(&hist[mono(v.y) >> 21], 1u);
            atomicAdd(&hist[mono(v.z) >> 21], 1u);
            atomicAdd(&hist[mono(v.w) >> 21], 1u);
        }
        __syncthreads();
        scan_find(hist, warpsum, tid, s_bin, s_rank);
        const int cb2 = s_bin[2];
        for (int i = tid; i < NV4; i += NTHREADS) {
            float4 v = row4[i];
            float vals[4] = {v.x, v.y, v.z, v.w};
            int b4 = 4 * i;
#pragma unroll
            for (int j = 0; j < 4; j++) {
                unsigned m = mono(vals[j]);
                if ((int)(m >> 21) >= cb2) {
                    int p = atomicAdd(&s_nhot, 1);
                    if (p < HOTCAP)
                        hot[p] = ((unsigned long long)m << 32) | (unsigned)(~(b4 + j));
                }
            }
        }
        __syncthreads();
        nhot = (s_nhot < HOTCAP) ? s_nhot : HOTCAP;
        const int b0 = s_bin[0], b1 = s_bin[1], b2 = s_bin[2];
        for (int i = tid; i < nhot; i += NTHREADS) {
            unsigned long long k = hot[i];
            int bin = (int)(k >> 53);
            bool m0 = (bin == b0), m1 = (bin == b1), m2 = (bin == b2);
            if (m0 | m1 | m2) {
                int cnt = 0;
                for (int j = 0; j < nhot; j++) {
                    unsigned long long kj = hot[j];
                    if ((int)(kj >> 53) == bin && kj > k) cnt++;
                }
                int r = cnt + 1;
                if (m0 && r == s_rank[0]) Tkey[0] = k;
                if (m1 && r == s_rank[1]) Tkey[1] = k;
                if (m2 && r == s_rank[2]) Tkey[2] = k;
            }
        }
        __syncthreads();
    }

    const unsigned long long T0 = Tkey[0], T1 = Tkey[1], T2 = Tkey[2];

    // ------- Dot phase: results buffered in SMEM (reuse hist region) --------
    unsigned long long* res = (unsigned long long*)hist;   // 1024 slots >= CUT2
    const int wid = tid >> 5;
    const int NW = NTHREADS / 32;
    const float4* emb4 = (const float4*)emb;
    const float4* rh4  = (const float4*)rh;

    for (int s = wid * 2; s < nhot; s += NW * 2) {
        unsigned long long k[2];
        bool act[2];
        unsigned idx[2];
        float4 e[2];
        int seg[2];
#pragma unroll
        for (int j = 0; j < 2; j++) {
            int si = s + j;
            k[j] = (si < nhot) ? hot[si] : 0ull;
            act[j] = (k[j] >= T2);
            if (act[j]) {
                seg[j] = (k[j] >= T0) ? 0 : ((k[j] >= T1) ? 1 : 2);
                idx[j] = ~(unsigned)k[j];
                e[j] = emb4[(size_t)idx[j] * (DIM / 4) + lane];
            }
        }
#pragma unroll
        for (int j = 0; j < 2; j++) {
            if (!act[j]) continue;
            float4 r = rh4[seg[j] * (DIM / 4) + lane];
            float p = e[j].x * r.x + e[j].y * r.y + e[j].z * r.z + e[j].w * r.w;
            p += __shfl_xor_sync(0xFFFFFFFFu, p, 16);
            p += __shfl_xor_sync(0xFFFFFFFFu, p, 8);
            p += __shfl_xor_sync(0xFFFFFFFFu, p, 4);
            p += __shfl_xor_sync(0xFFFFFFFFu, p, 2);
            p += __shfl_xor_sync(0xFFFFFFFFu, p, 1);
            if (lane == 0) {
                int slot = atomicAdd(&s_dcnt, 1);
                if (slot < CUT2)
                    res[slot] = ((unsigned long long)idx[j] << 32) | __float_as_uint(p);
            }
        }
    }
    __syncthreads();                                   // res complete

    // ------- Scatter after all TMA stores have fully landed -----------------
    if (tid == 0)
        asm volatile("cp.async.bulk.wait_group 0;" ::: "memory");
    __syncthreads();
    int dcnt = (s_dcnt < CUT2) ? s_dcnt : CUT2;
    for (int i = tid; i < dcnt; i += NTHREADS) {
        unsigned long long r = res[i];
        outrow[(unsigned)(r >> 32)] = __uint_as_float((unsigned)r);
    }
}

extern "C" void kernel_launch(void* const* d_in, const int* in_sizes, int n_in,
                              void* d_out, int out_size)
{
    const float* hidden = nullptr;
    const float* logits = nullptr;
    const float* emb    = nullptr;
    const float* W      = nullptr;
    const float* bias   = nullptr;
    for (int i = 0; i < n_in; i++) {
        switch (in_sizes[i]) {
            case BATCH * DIM:      hidden = (const float*)d_in[i]; break;
            case BATCH * VOCAB:    logits = (const float*)d_in[i]; break;
            case VOCAB * DIM:      emb    = (const float*)d_in[i]; break;
            case NSEG * DIM * DIM: W      = (const float*)d_in[i]; break;
            case NSEG * DIM:       bias   = (const float*)d_in[i]; break;
        }
    }
    float* out = (float*)d_out;

    rh_kernel<<<dim3(BATCH / RTILE, NSEG), 256>>>(hidden, W, bias);
    rerank_tma_kernel<<<BATCH, NTHREADS>>>(logits, emb, out);
}

// round 9
// speedup vs baseline: 3.0194x; 3.0194x over previous
#include <cuda_runtime.h>
#include <cstdint>

#define BATCH    1024
#define VOCAB    100000
#define DIM      128
#define NSEG     3
#define NBINS    4096
#define HOTCAP   3072
#define BCAP     96
#define NTHREADS 512
#define CUT0 100
#define CUT1 500
#define CUT2 1000
#define TGUESS 2.0f          // rank-1000 of 100k N(0,1) ~ 2.33; P(v>2)~2.3% -> ~2275 cands

__device__ float g_rh[NSEG * BATCH * DIM];

// ---------------------------------------------------------------------------
// Kernel 1: rerank_hidden = hidden @ W[seg]^T + b[seg], tiled smem GEMM.
// ---------------------------------------------------------------------------
#define RTILE 32
#define KC 64
__global__ void __launch_bounds__(256)
rh_kernel(const float* __restrict__ hidden,
          const float* __restrict__ W,
          const float* __restrict__ bias)
{
    __shared__ float Wt[DIM][KC + 1];
    __shared__ float hs[RTILE][KC];
    const int seg = blockIdx.y;
    const int r0  = blockIdx.x * RTILE;
    const int t   = threadIdx.x;
    const int d   = t & 127;
    const int rhh = t >> 7;

    float acc[16];
#pragma unroll
    for (int i = 0; i < 16; i++) acc[i] = 0.f;
    const float* Wseg = W + (size_t)seg * DIM * DIM;

    for (int kc = 0; kc < DIM; kc += KC) {
        __syncthreads();
#pragma unroll
        for (int j = 0; j < 32; j++) {
            int e = t + j * 256;
            Wt[e >> 6][e & 63] = Wseg[(e >> 6) * DIM + kc + (e & 63)];
        }
#pragma unroll
        for (int j = 0; j < 8; j++) {
            int e = t + j * 256;
            hs[e >> 6][e & 63] = hidden[(size_t)(r0 + (e >> 6)) * DIM + kc + (e & 63)];
        }
        __syncthreads();
#pragma unroll 8
        for (int k = 0; k < KC; k++) {
            float wv = Wt[d][k];
#pragma unroll
            for (int r = 0; r < 16; r++)
                acc[r] += hs[rhh * 16 + r][k] * wv;
        }
    }
    float bv = bias[seg * DIM + d];
#pragma unroll
    for (int r = 0; r < 16; r++) {
        int row = r0 + rhh * 16 + r;
        g_rh[(size_t)seg * BATCH * DIM + (size_t)row * DIM + d] = acc[r] + bv;
    }
}

__device__ __forceinline__ unsigned mono(float f) {
    unsigned u = __float_as_uint(f);
    return (u & 0x80000000u) ? ~u : (u | 0x80000000u);
}

__device__ __forceinline__ unsigned finebin(unsigned m) {
    unsigned fb = (m - 0xC0000000u) >> 12;       // BASE = mono(2.0f)
    return (fb > (NBINS - 1u)) ? (NBINS - 1u) : fb;
}

// ---------------------------------------------------------------------------
// Scan NBINS-bin histogram descending with shfl; 8 bins per thread.
// ---------------------------------------------------------------------------
__device__ void scan_find(unsigned* hist, unsigned* warpsum, int tid,
                          int* s_bin, int* s_rank)
{
    const int lane = tid & 31, w = tid >> 5;
    unsigned c[8];
    unsigned chunk = 0;
#pragma unroll
    for (int j = 0; j < 8; j++) {
        c[j] = hist[NBINS - 1 - 8 * tid - j];
        chunk += c[j];
    }
    unsigned pfx = chunk;
#pragma unroll
    for (int off = 1; off < 32; off <<= 1) {
        unsigned n = __shfl_up_sync(0xFFFFFFFFu, pfx, off);
        if (lane >= off) pfx += n;
    }
    if (lane == 31) warpsum[w] = pfx;
    __syncthreads();
    if (w == 0) {
        unsigned s = (lane < 16) ? warpsum[lane] : 0u;
#pragma unroll
        for (int off = 1; off < 16; off <<= 1) {
            unsigned n = __shfl_up_sync(0xFFFFFFFFu, s, off);
            if (lane >= off) s += n;
        }
        if (lane < 16) warpsum[lane] = s;
    }
    __syncthreads();
    unsigned wbase = (w > 0) ? warpsum[w - 1] : 0u;
    unsigned incl = wbase + pfx;
    unsigned excl = incl - chunk;
    const unsigned Ks[3] = {CUT0, CUT1, CUT2};
#pragma unroll
    for (int kk = 0; kk < 3; kk++) {
        unsigned K = Ks[kk];
        if (excl < K && K <= incl) {
            unsigned cc = excl;
#pragma unroll
            for (int j = 0; j < 8; j++) {
                unsigned h = c[j];
                if (cc < K && K <= cc + h) {
                    s_bin[kk]  = NBINS - 1 - 8 * tid - j;
                    s_rank[kk] = (int)(K - cc);
                    break;
                }
                cc += h;
            }
        }
    }
    __syncthreads();
}

__device__ __forceinline__ void push_cand(float v, int gi,
                                          unsigned long long* hot, unsigned* hist,
                                          int& slot)
{
    unsigned m = mono(v);
    if (slot < HOTCAP) {
        hot[slot] = ((unsigned long long)m << 32) | (unsigned)(~gi);
        atomicAdd(&hist[finebin(m)], 1u);
    }
    slot++;
}

__device__ __forceinline__ void push_group(float4 v, unsigned m4, int gi,
                                           unsigned long long* hot, unsigned* hist,
                                           int& slot)
{
    if (m4 & 1) push_cand(v.x, gi + 0, hot, hist, slot);
    if (m4 & 2) push_cand(v.y, gi + 1, hot, hist, slot);
    if (m4 & 4) push_cand(v.z, gi + 2, hot, hist, slot);
    if (m4 & 8) push_cand(v.w, gi + 3, hot, hist, slot);
}

// ---------------------------------------------------------------------------
// Kernel 2: one CTA (512 thr) per row; fused copy + collect + select + dot.
// ---------------------------------------------------------------------------
__global__ void __launch_bounds__(NTHREADS, 4)
rerank_kernel(const float* __restrict__ logits,
              const float* __restrict__ emb,
              float* __restrict__ out)
{
    __shared__ unsigned long long hot[HOTCAP];       // 24 KB
    __shared__ unsigned hist[NBINS];                 // 16 KB
    __shared__ unsigned long long bbuf[3][BCAP];     // 2.25 KB boundary-bin members
    __shared__ unsigned warpsum[16];
    __shared__ float rh[NSEG * DIM];
    __shared__ unsigned long long Tkey[3];
    __shared__ int s_bin[3];
    __shared__ int s_rank[3];
    __shared__ int bcnt[3];
    __shared__ int s_nhot;

    const int row = blockIdx.x;
    const int tid = threadIdx.x;
    const int lane = tid & 31;

    for (int i = tid; i < NBINS; i += NTHREADS) hist[i] = 0u;
    if (tid < NSEG * DIM) {
        int seg = tid >> 7, d = tid & 127;
        rh[tid] = g_rh[(size_t)seg * BATCH * DIM + (size_t)row * DIM + d];
    }
    if (tid == 0) { s_nhot = 0; }
    if (tid < 3) bcnt[tid] = 0;
    __syncthreads();

    const float4* row4 = (const float4*)(logits + (size_t)row * VOCAB);
    float4*       out4 = (float4*)(out + (size_t)row * VOCAB);
    const int NV4 = VOCAB / 4;   // 25000

    // ------- Pass 1: 2-way batched stream copy + warp-aggregated collect -----
    for (int base = 0; base < NV4; base += NTHREADS * 2) {
        int i0 = base + tid;
        int i1 = base + NTHREADS + tid;
        bool ok0 = i0 < NV4, ok1 = i1 < NV4;
        float4 v0, v1;
        if (ok0) v0 = __ldcs(&row4[i0]);
        if (ok1) v1 = __ldcs(&row4[i1]);
        if (ok0) __stcs(&out4[i0], v0);
        if (ok1) __stcs(&out4[i1], v1);

        // fmax prefilter (3+3 FMNMX + 1 FMNMX + 1 FSETP on the common path)
        float M0 = ok0 ? fmaxf(fmaxf(v0.x, v0.y), fmaxf(v0.z, v0.w)) : -1e30f;
        float M1 = ok1 ? fmaxf(fmaxf(v1.x, v1.y), fmaxf(v1.z, v1.w)) : -1e30f;
        unsigned msk = 0;
        int cnt = 0;
        if (fmaxf(M0, M1) > TGUESS) {
            if (M0 > TGUESS)
                msk |= (v0.x > TGUESS) | ((v0.y > TGUESS) << 1)
                     | ((v0.z > TGUESS) << 2) | ((v0.w > TGUESS) << 3);
            if (M1 > TGUESS)
                msk |= ((v1.x > TGUESS) << 4) | ((v1.y > TGUESS) << 5)
                     | ((v1.z > TGUESS) << 6) | ((v1.w > TGUESS) << 7);
            cnt = __popc(msk);
        }

        if (__ballot_sync(0xFFFFFFFFu, cnt > 0)) {
            int pfx = cnt;
#pragma unroll
            for (int off = 1; off < 32; off <<= 1) {
                int n = __shfl_up_sync(0xFFFFFFFFu, pfx, off);
                if (lane >= off) pfx += n;
            }
            int total = __shfl_sync(0xFFFFFFFFu, pfx, 31);
            int wbase = 0;
            if (lane == 31) wbase = atomicAdd(&s_nhot, total);
            wbase = __shfl_sync(0xFFFFFFFFu, wbase, 31);
            int slot = wbase + pfx - cnt;
            if (cnt) {
                push_group(v0, msk & 0xF,        4 * i0, hot, hist, slot);
                push_group(v1, (msk >> 4) & 0xF, 4 * i1, hot, hist, slot);
            }
        }
    }
    __syncthreads();

    int nhot = s_nhot;
    bool fast = (nhot >= CUT2) && (nhot <= HOTCAP);

    if (fast) {
        scan_find(hist, warpsum, tid, s_bin, s_rank);
        const int b0 = s_bin[0], b1 = s_bin[1], b2 = s_bin[2];

        // ---- Gather boundary-bin members into tiny buffers (one pass) ----
        for (int i = tid; i < nhot; i += NTHREADS) {
            unsigned long long k = hot[i];
            int bin = (int)finebin((unsigned)(k >> 32));
            if (bin == b0) { int p = atomicAdd(&bcnt[0], 1); if (p < BCAP) bbuf[0][p] = k; }
            if (bin == b1) { int p = atomicAdd(&bcnt[1], 1); if (p < BCAP) bbuf[1][p] = k; }
            if (bin == b2) { int p = atomicAdd(&bcnt[2], 1); if (p < BCAP) bbuf[2][p] = k; }
        }
        __syncthreads();

        // ---- Exact threshold keys: count-greater within each tiny buffer ----
#pragma unroll
        for (int kk = 0; kk < 3; kk++) {
            int n = bcnt[kk];
            if (n <= BCAP) {
                for (int i = tid; i < n; i += NTHREADS) {
                    unsigned long long k = bbuf[kk][i];
                    int cnt = 0;
                    for (int j = 0; j < n; j++)
                        if (bbuf[kk][j] > k) cnt++;
                    if (cnt + 1 == s_rank[kk]) Tkey[kk] = k;
                }
            } else {
                // overflow (astronomically rare): scan the full hot[] set
                const int bk = s_bin[kk];
                for (int i = tid; i < nhot; i += NTHREADS) {
                    unsigned long long k = hot[i];
                    if ((int)finebin((unsigned)(k >> 32)) != bk) continue;
                    int cnt = 0;
                    for (int j = 0; j < nhot; j++) {
                        unsigned long long kj = hot[j];
                        if ((int)finebin((unsigned)(kj >> 32)) == bk && kj > k) cnt++;
                    }
                    if (cnt + 1 == s_rank[kk]) Tkey[kk] = k;
                }
            }
        }
        __syncthreads();
    } else {
        // ------- Fallback: full coarse histogram over the row (rare) -------
        for (int i = tid; i < NBINS; i += NTHREADS) hist[i] = 0u;
        if (tid == 0) s_nhot = 0;
        __syncthreads();
        for (int i = tid; i < NV4; i += NTHREADS) {
            float4 v = row4[i];
            atomicAdd(&hist[mono(v.x) >> 20], 1u);
            atomicAdd(&hist[mono(v.y) >> 20], 1u);
            atomicAdd(&hist[mono(v.z) >> 20], 1u);
            atomicAdd(&hist[mono(v.w) >> 20], 1u);
        }
        __syncthreads();
        scan_find(hist, warpsum, tid, s_bin, s_rank);
        const int cb2 = s_bin[2];
        for (int i = tid; i < NV4; i += NTHREADS) {
            float4 v = row4[i];
            float vals[4] = {v.x, v.y, v.z, v.w};
            int b4 = 4 * i;
#pragma unroll
            for (int j = 0; j < 4; j++) {
                unsigned m = mono(vals[j]);
                if ((int)(m >> 20) >= cb2) {
                    int p = atomicAdd(&s_nhot, 1);
                    if (p < HOTCAP)
                        hot[p] = ((unsigned long long)m << 32) | (unsigned)(~(b4 + j));
                }
            }
        }
        __syncthreads();
        nhot = (s_nhot < HOTCAP) ? s_nhot : HOTCAP;
        const int b0 = s_bin[0], b1 = s_bin[1], b2 = s_bin[2];
        for (int i = tid; i < nhot; i += NTHREADS) {
            unsigned long long k = hot[i];
            int bin = (int)(k >> 52);
            bool m0 = (bin == b0), m1 = (bin == b1), m2 = (bin == b2);
            if (m0 | m1 | m2) {
                int cnt = 0;
                for (int j = 0; j < nhot; j++) {
                    unsigned long long kj = hot[j];
                    if ((int)(kj >> 52) == bin && kj > k) cnt++;
                }
                int r = cnt + 1;
                if (m0 && r == s_rank[0]) Tkey[0] = k;
                if (m1 && r == s_rank[1]) Tkey[1] = k;
                if (m2 && r == s_rank[2]) Tkey[2] = k;
            }
        }
        __syncthreads();
    }

    const unsigned long long T0 = Tkey[0], T1 = Tkey[1], T2 = Tkey[2];

    // ------- Dot phase: 2 candidates per warp per round -------
    const int wid = tid >> 5;
    const int NW = NTHREADS / 32;
    const float4* emb4 = (const float4*)emb;
    const float4* rh4  = (const float4*)rh;
    float* outrow = out + (size_t)row * VOCAB;

    for (int s = wid * 2; s < nhot; s += NW * 2) {
        unsigned long long k[2];
        bool act[2];
        unsigned idx[2];
        float4 e[2];
        int seg[2];
#pragma unroll
        for (int j = 0; j < 2; j++) {
            int si = s + j;
            k[j] = (si < nhot) ? hot[si] : 0ull;
            act[j] = (k[j] >= T2);
            if (act[j]) {
                seg[j] = (k[j] >= T0) ? 0 : ((k[j] >= T1) ? 1 : 2);
                idx[j] = ~(unsigned)k[j];
                e[j] = emb4[(size_t)idx[j] * (DIM / 4) + lane];
            }
        }
#pragma unroll
        for (int j = 0; j < 2; j++) {
            if (!act[j]) continue;
            float4 r = rh4[seg[j] * (DIM / 4) + lane];
            float p = e[j].x * r.x + e[j].y * r.y + e[j].z * r.z + e[j].w * r.w;
            p += __shfl_xor_sync(0xFFFFFFFFu, p, 16);
            p += __shfl_xor_sync(0xFFFFFFFFu, p, 8);
            p += __shfl_xor_sync(0xFFFFFFFFu, p, 4);
            p += __shfl_xor_sync(0xFFFFFFFFu, p, 2);
            p += __shfl_xor_sync(0xFFFFFFFFu, p, 1);
            if (lane == 0) outrow[idx[j]] = p;
        }
    }
}

extern "C" void kernel_launch(void* const* d_in, const int* in_sizes, int n_in,
                              void* d_out, int out_size)
{
    const float* hidden = nullptr;
    const float* logits = nullptr;
    const float* emb    = nullptr;
    const float* W      = nullptr;
    const float* bias   = nullptr;
    for (int i = 0; i < n_in; i++) {
        switch (in_sizes[i]) {
            case BATCH * DIM:      hidden = (const float*)d_in[i]; break;
            case BATCH * VOCAB:    logits = (const float*)d_in[i]; break;
            case VOCAB * DIM:      emb    = (const float*)d_in[i]; break;
            case NSEG * DIM * DIM: W      = (const float*)d_in[i]; break;
            case NSEG * DIM:       bias   = (const float*)d_in[i]; break;
        }
    }
    float* out = (float*)d_out;

    rh_kernel<<<dim3(BATCH / RTILE, NSEG), 256>>>(hidden, W, bias);
    rerank_kernel<<<BATCH, NTHREADS>>>(logits, emb, out);
}